// round 5
// baseline (speedup 1.0000x reference)
#include <cuda_runtime.h>
#include <cstdint>

#define B_   64
#define T_   512
#define I_   512
#define H_   512
#define G4   2048
#define NC   64
#define BG4  (B_ * G4)

// ------------------------- device scratch ----------------------------------
__device__ float  g_WxHi[I_ * G4];                    // [k][n] tf32 hi
__device__ float  g_WxLo[I_ * G4];                    // [k][n] tf32 lo
__device__ float  g_bias[G4];
__device__ float  g_xproj[(size_t)T_ * BG4];          // [t][b][n] = x@Wx + bias (fp32)
__device__ float  g_hall[(size_t)(T_ + 1) * (B_ * H_)];  // h_t fp32, per-step buffer
__device__ int    g_count;                            // grid barrier (monotonic)

// ------------------------- helpers -----------------------------------------
__device__ __forceinline__ float to_tf32(float x) {
    uint32_t u;
    asm("cvt.rna.tf32.f32 %0, %1;" : "=r"(u) : "f"(x));
    return __uint_as_float(u);
}
__device__ __forceinline__ float2 split2(float v) {
    float hi = to_tf32(v);
    float lo = to_tf32(v - hi);
    return make_float2(hi, lo);
}
__device__ __forceinline__ uint32_t fu(float x) { return __float_as_uint(x); }

__device__ __forceinline__ float sigm(float x) { return 1.0f / (1.0f + __expf(-x)); }
__device__ __forceinline__ float tanh_acc(float x) {
    return 1.0f - 2.0f / (__expf(2.0f * x) + 1.0f);
}

__device__ __forceinline__ int ld_cg_int(const int* p) {
    int v;
    asm volatile("ld.global.cg.b32 %0, [%1];" : "=r"(v) : "l"(p));
    return v;
}

__device__ __forceinline__ void mma_tf32(float (&d)[4], const uint32_t (&a)[4],
                                         uint32_t b0, uint32_t b1) {
    asm volatile(
        "mma.sync.aligned.m16n8k8.row.col.f32.tf32.tf32.f32 "
        "{%0,%1,%2,%3}, {%4,%5,%6,%7}, {%8,%9}, {%0,%1,%2,%3};"
        : "+f"(d[0]), "+f"(d[1]), "+f"(d[2]), "+f"(d[3])
        : "r"(a[0]), "r"(a[1]), "r"(a[2]), "r"(a[3]), "r"(b0), "r"(b1));
}

__device__ __forceinline__ const float* wsel(int gate, const float* Wf, const float* Wi,
                                             const float* Wo, const float* Wc) {
    return gate == 0 ? Wf : gate == 1 ? Wi : gate == 2 ? Wo : Wc;
}

// ------------------------- K0: pack ----------------------------------------
__global__ void pack_kernel(const float* __restrict__ Wf, const float* __restrict__ Wi,
                            const float* __restrict__ Wo, const float* __restrict__ Wc,
                            const float* __restrict__ bf, const float* __restrict__ bi,
                            const float* __restrict__ bo, const float* __restrict__ bc) {
    int idx = blockIdx.x * blockDim.x + threadIdx.x;
    if (idx < I_ * G4) {
        int n = idx & (G4 - 1), k = idx >> 11;
        int gate = n >> 9, j = n & 511;
        const float* W = wsel(gate, Wf, Wi, Wo, Wc);
        float2 s = split2(W[(size_t)k * H_ + j]);
        g_WxHi[idx] = s.x;
        g_WxLo[idx] = s.y;
    }
    if (idx < G4) {
        int gate = idx >> 9, j = idx & 511;
        const float* b = gate == 0 ? bf : gate == 1 ? bi : gate == 2 ? bo : bc;
        g_bias[idx] = b[j];
    }
    if (idx < B_ * H_) g_hall[idx] = 0.0f;      // h_0 = 0
    if (idx == 0) g_count = 0;                  // reset grid barrier each launch
}

// ------------------------- K1: xproj = X @ Wx + bias (3xTF32) --------------
// C[32768, 2048]; BM=64 (batch), BN=64, BK=32. grid (32, 512). 4 warps.
#define K1_SMEM ((4 * 2 * 2304) * 4)
__global__ void __launch_bounds__(128) xproj_kernel(const float* __restrict__ x) {
    extern __shared__ float sm1[];
    float* sAhi = sm1;             // [2][64*36]
    float* sAlo = sm1 + 4608;
    float* sBhi = sm1 + 9216;      // [2][32*72]
    float* sBlo = sm1 + 13824;

    const int tid = threadIdx.x;
    const int bx = blockIdx.x, by = blockIdx.y;
    const int lane = tid & 31, w = tid >> 5;
    const int g = lane >> 2, tg = lane & 3;
    const int mw = w & 1, nw = w >> 1;

    const int ar = tid >> 3, ac = (tid & 7) * 4;
    const int br = tid >> 4, bc = (tid & 15) * 4;
    const float* Abase = x + (size_t)ar * (T_ * I_) + (size_t)by * I_ + ac;
    const float* BHbase = g_WxHi + (size_t)br * G4 + bx * 64 + bc;
    const float* BLbase = g_WxLo + (size_t)br * G4 + bx * 64 + bc;

    float4 ra[4], rbh[4], rbl[4];
#pragma unroll
    for (int i = 0; i < 4; i++) {
        ra[i]  = __ldg((const float4*)(Abase + (size_t)(16 * i) * (T_ * I_)));
        rbh[i] = __ldg((const float4*)(BHbase + (size_t)(8 * i) * G4));
        rbl[i] = __ldg((const float4*)(BLbase + (size_t)(8 * i) * G4));
    }
#pragma unroll
    for (int i = 0; i < 4; i++) {
        float2 sx = split2(ra[i].x), sy = split2(ra[i].y);
        float2 sz = split2(ra[i].z), sw = split2(ra[i].w);
        *(float4*)&sAhi[(ar + 16 * i) * 36 + ac] = make_float4(sx.x, sy.x, sz.x, sw.x);
        *(float4*)&sAlo[(ar + 16 * i) * 36 + ac] = make_float4(sx.y, sy.y, sz.y, sw.y);
        *(float4*)&sBhi[(br + 8 * i) * 72 + bc] = rbh[i];
        *(float4*)&sBlo[(br + 8 * i) * 72 + bc] = rbl[i];
    }
    __syncthreads();

    float acc[2][4][4] = {};

    for (int kc = 0; kc < 16; kc++) {
        const int cb = kc & 1;
        const int abuf = cb * 2304, bbuf = cb * 2304;
        if (kc < 15) {
#pragma unroll
            for (int i = 0; i < 4; i++) {
                ra[i]  = __ldg((const float4*)(Abase + (size_t)(16 * i) * (T_ * I_) + (kc + 1) * 32));
                rbh[i] = __ldg((const float4*)(BHbase + (size_t)((kc + 1) * 32 + 8 * i) * G4));
                rbl[i] = __ldg((const float4*)(BLbase + (size_t)((kc + 1) * 32 + 8 * i) * G4));
            }
        }
#pragma unroll
        for (int kk = 0; kk < 32; kk += 8) {
            uint32_t ahi[2][4], alo[2][4];
#pragma unroll
            for (int mf = 0; mf < 2; mf++) {
                int r0 = mw * 32 + mf * 16 + g;
                ahi[mf][0] = fu(sAhi[abuf + r0 * 36 + kk + tg]);
                ahi[mf][1] = fu(sAhi[abuf + (r0 + 8) * 36 + kk + tg]);
                ahi[mf][2] = fu(sAhi[abuf + r0 * 36 + kk + tg + 4]);
                ahi[mf][3] = fu(sAhi[abuf + (r0 + 8) * 36 + kk + tg + 4]);
                alo[mf][0] = fu(sAlo[abuf + r0 * 36 + kk + tg]);
                alo[mf][1] = fu(sAlo[abuf + (r0 + 8) * 36 + kk + tg]);
                alo[mf][2] = fu(sAlo[abuf + r0 * 36 + kk + tg + 4]);
                alo[mf][3] = fu(sAlo[abuf + (r0 + 8) * 36 + kk + tg + 4]);
            }
#pragma unroll
            for (int nf = 0; nf < 4; nf++) {
                int col = nw * 32 + nf * 8 + g;
                uint32_t bh0 = fu(sBhi[bbuf + (kk + tg) * 72 + col]);
                uint32_t bh1 = fu(sBhi[bbuf + (kk + tg + 4) * 72 + col]);
                uint32_t bl0 = fu(sBlo[bbuf + (kk + tg) * 72 + col]);
                uint32_t bl1 = fu(sBlo[bbuf + (kk + tg + 4) * 72 + col]);
#pragma unroll
                for (int mf = 0; mf < 2; mf++) {
                    mma_tf32(acc[mf][nf], ahi[mf], bh0, bh1);
                    mma_tf32(acc[mf][nf], ahi[mf], bl0, bl1);
                    mma_tf32(acc[mf][nf], alo[mf], bh0, bh1);
                }
            }
        }
        if (kc < 15) {
            const int nb = (cb ^ 1) * 2304;
#pragma unroll
            for (int i = 0; i < 4; i++) {
                float2 sx = split2(ra[i].x), sy = split2(ra[i].y);
                float2 sz = split2(ra[i].z), sw = split2(ra[i].w);
                *(float4*)&sAhi[nb + (ar + 16 * i) * 36 + ac] = make_float4(sx.x, sy.x, sz.x, sw.x);
                *(float4*)&sAlo[nb + (ar + 16 * i) * 36 + ac] = make_float4(sx.y, sy.y, sz.y, sw.y);
                *(float4*)&sBhi[nb + (br + 8 * i) * 72 + bc] = rbh[i];
                *(float4*)&sBlo[nb + (br + 8 * i) * 72 + bc] = rbl[i];
            }
            __syncthreads();
        }
    }

    const size_t outbase = (size_t)by * BG4;
#pragma unroll
    for (int mf = 0; mf < 2; mf++)
#pragma unroll
        for (int nf = 0; nf < 4; nf++) {
            int r = mw * 32 + mf * 16 + g;
            int cg = bx * 64 + nw * 32 + nf * 8 + tg * 2;
            float2 bb = *(const float2*)&g_bias[cg];
            float2 v0 = {acc[mf][nf][0] + bb.x, acc[mf][nf][1] + bb.y};
            float2 v1 = {acc[mf][nf][2] + bb.x, acc[mf][nf][3] + bb.y};
            *(float2*)&g_xproj[outbase + (size_t)r * G4 + cg] = v0;
            *(float2*)&g_xproj[outbase + (size_t)(r + 8) * G4 + cg] = v1;
        }
}

// ------------------------- K2: persistent recurrence (3xTF32) ---------------
// 64 CTAs x 128 thr. CTA nc owns hidden units [8nc,8nc+8) x 4 gates.
// Per-step GRID BARRIER (monotonic counter) replaces the chunk-flag pipeline:
// all h_t stores are globally visible before any CTA reads any h_t chunk.
#define SWF_F4   8192
#define SH_STR   68
#define SH_PLANE (64 * SH_STR)
#define SMEM2    (SWF_F4 * 16 + 2 * SH_PLANE * 4)

__global__ void __launch_bounds__(128, 1) lstm_kernel(
    float* __restrict__ out,
    const float* __restrict__ Wf, const float* __restrict__ Wi,
    const float* __restrict__ Wo, const float* __restrict__ Wc) {
    extern __shared__ float smem[];
    float4* sWf = (float4*)smem;                // [8192] float4 frag-major Wh
    float*  sH  = smem + SWF_F4 * 4;            // [2][64][SH_STR] fp32 h chunk

    const int tid = threadIdx.x;
    const int nc = blockIdx.x;
    const int lane = tid & 31, w = tid >> 5;
    const int g = lane >> 2, tg = lane & 3;
    const int w16 = w * 16;
    const int j0 = nc * 8 + tg * 2;
    const int hb = tid >> 4, hk4 = tid & 15;    // h loader: b, float4-of-k

    // ---- build Wh fragments in smem (warp w handles kc = 2w, 2w+1) ----
    // Fragment contract (mma row.col): b0 = B[k=tg][n=g], b1 = B[k=tg+4][n=g],
    // where B[k][n] = W[(I_+k)][nc*8+n]. Stored as {b0hi, b1hi, b0lo, b1lo}.
#pragma unroll
    for (int kci = 0; kci < 2; kci++) {
        const int kc = w * 2 + kci;
#pragma unroll
        for (int kk8 = 0; kk8 < 8; kk8++) {
            const int k0 = kc * 64 + kk8 * 8 + tg;
#pragma unroll
            for (int nf = 0; nf < 4; nf++) {
                const float* W = wsel(nf, Wf, Wi, Wo, Wc);
                float v0 = __ldg(&W[(size_t)(I_ + k0) * H_ + nc * 8 + g]);
                float v1 = __ldg(&W[(size_t)(I_ + k0 + 4) * H_ + nc * 8 + g]);
                float2 s0 = split2(v0), s1 = split2(v1);
                sWf[(kc * 32 + kk8 * 4 + nf) * 32 + lane] =
                    make_float4(s0.x, s1.x, s0.y, s1.y);
            }
        }
    }
    __syncthreads();

    float cs[4] = {0.0f, 0.0f, 0.0f, 0.0f};

    // xproj prefetch for t = 0
    float2 xp[8];
#pragma unroll
    for (int gate = 0; gate < 4; gate++)
#pragma unroll
        for (int rr = 0; rr < 2; rr++) {
            int b = w16 + g + rr * 8;
            xp[gate * 2 + rr] =
                __ldg((const float2*)(g_xproj + (size_t)b * G4 + gate * 512 + j0));
        }

    for (int t = 0; t < T_; t++) {
        // h_t fully visible here (kernel ordering for t=0; grid barrier for t>0)
        const float* hsrc = g_hall + (size_t)t * (B_ * H_);

        float4 hreg[8];
#pragma unroll
        for (int r = 0; r < 8; r++)               // prologue: chunk 0
            hreg[r] = __ldcg((const float4*)(hsrc + (size_t)(hb + r * 8) * 512 + hk4 * 4));
#pragma unroll
        for (int r = 0; r < 8; r++)
            *(float4*)&sH[(hb + r * 8) * SH_STR + hk4 * 4] = hreg[r];
        __syncthreads();

        float acc[4][4] = {};

        for (int kc = 0; kc < 8; kc++) {
            const int cb = kc & 1;
            if (kc < 7) {                         // prefetch chunk kc+1
#pragma unroll
                for (int r = 0; r < 8; r++)
                    hreg[r] = __ldcg((const float4*)(hsrc + (size_t)(hb + r * 8) * 512 +
                                                     (kc + 1) * 64 + hk4 * 4));
            }
            // compute chunk kc
            const float* sA = sH + cb * SH_PLANE;
            const int r0 = w16 + g;
#pragma unroll
            for (int kk8 = 0; kk8 < 8; kk8++) {
                const int kb = kk8 * 8;
                float h0 = sA[r0 * SH_STR + kb + tg];
                float h1 = sA[(r0 + 8) * SH_STR + kb + tg];
                float h2 = sA[r0 * SH_STR + kb + tg + 4];
                float h3 = sA[(r0 + 8) * SH_STR + kb + tg + 4];
                float2 q0 = split2(h0), q1 = split2(h1);
                float2 q2 = split2(h2), q3 = split2(h3);
                uint32_t ahi[4] = {fu(q0.x), fu(q1.x), fu(q2.x), fu(q3.x)};
                uint32_t alo[4] = {fu(q0.y), fu(q1.y), fu(q2.y), fu(q3.y)};
                const float4* wfb = sWf + (kc * 32 + kk8 * 4) * 32 + lane;
#pragma unroll
                for (int nf = 0; nf < 4; nf++) {
                    float4 wf = wfb[nf * 32];
                    mma_tf32(acc[nf], ahi, fu(wf.x), fu(wf.y));
                    mma_tf32(acc[nf], ahi, fu(wf.z), fu(wf.w));
                    mma_tf32(acc[nf], alo, fu(wf.x), fu(wf.y));
                }
            }
            if (kc < 7) {                         // store chunk kc+1 into other buffer
                float* dst = sH + (cb ^ 1) * SH_PLANE;
#pragma unroll
                for (int r = 0; r < 8; r++)
                    *(float4*)&dst[(hb + r * 8) * SH_STR + hk4 * 4] = hreg[r];
            }
            __syncthreads();
        }

        // ---- epilogue: gates + state update ----
        float hout[4];
#pragma unroll
        for (int rr = 0; rr < 2; rr++) {
#pragma unroll
            for (int p = 0; p < 2; p++) {
                int q = rr * 2 + p;
                float xf = p == 0 ? xp[0 + rr].x : xp[0 + rr].y;
                float xi = p == 0 ? xp[2 + rr].x : xp[2 + rr].y;
                float xo = p == 0 ? xp[4 + rr].x : xp[4 + rr].y;
                float xc = p == 0 ? xp[6 + rr].x : xp[6 + rr].y;
                float fg = sigm(acc[0][q] + xf);
                float ig = sigm(acc[1][q] + xi);
                float og = sigm(acc[2][q] + xo);
                float Cg = tanh_acc(acc[3][q] + xc);
                cs[q] = fg * cs[q] + ig * Cg;
                hout[q] = og * tanh_acc(cs[q]);
            }
        }

        if (t == T_ - 1) {
#pragma unroll
            for (int rr = 0; rr < 2; rr++) {
                int b = w16 + g + rr * 8;
                float2 v = {hout[rr * 2 + 0], hout[rr * 2 + 1]};
                *(float2*)&out[(size_t)b * H_ + j0] = v;
            }
            break;
        }

        // write h_{t+1}
        float* hdst = g_hall + (size_t)(t + 1) * (B_ * H_);
#pragma unroll
        for (int rr = 0; rr < 2; rr++) {
            int b = w16 + g + rr * 8;
            float2 v = {hout[rr * 2 + 0], hout[rr * 2 + 1]};
            __stcg((float2*)&hdst[(size_t)b * H_ + j0], v);
        }

        // ---- grid barrier (monotonic counter), xp prefetch in its shadow ----
        __threadfence();                          // release h stores
        __syncthreads();                          // whole CTA done + fenced
        if (tid == 0) atomicAdd(&g_count, 1);     // arrive

        {   // prefetch xproj for t+1 (independent of h)
            const float* xsrc = g_xproj + (size_t)(t + 1) * BG4;
#pragma unroll
            for (int gate = 0; gate < 4; gate++)
#pragma unroll
                for (int rr = 0; rr < 2; rr++) {
                    int b = w16 + g + rr * 8;
                    xp[gate * 2 + rr] =
                        __ldg((const float2*)(xsrc + (size_t)b * G4 + gate * 512 + j0));
                }
        }

        if (tid == 0) {
            while (ld_cg_int(&g_count) < NC * (t + 1)) {}
            __threadfence();                      // acquire
        }
        __syncthreads();
    }
}

// ------------------------- launch ------------------------------------------
extern "C" void kernel_launch(void* const* d_in, const int* in_sizes, int n_in,
                              void* d_out, int out_size) {
    (void)in_sizes; (void)n_in; (void)out_size;
    const float* x  = (const float*)d_in[0];
    const float* Wf = (const float*)d_in[1];
    const float* bf = (const float*)d_in[2];
    const float* Wi = (const float*)d_in[3];
    const float* bi = (const float*)d_in[4];
    const float* Wo = (const float*)d_in[5];
    const float* bo = (const float*)d_in[6];
    const float* Wc = (const float*)d_in[7];
    const float* bc = (const float*)d_in[8];

    cudaFuncSetAttribute(xproj_kernel, cudaFuncAttributeMaxDynamicSharedMemorySize, K1_SMEM);
    cudaFuncSetAttribute(lstm_kernel, cudaFuncAttributeMaxDynamicSharedMemorySize, SMEM2);

    pack_kernel<<<4096, 256>>>(Wf, Wi, Wo, Wc, bf, bi, bo, bc);
    dim3 gx(32, 512);
    xproj_kernel<<<gx, 128, K1_SMEM>>>(x);
    lstm_kernel<<<NC, 128, SMEM2>>>((float*)d_out, Wf, Wi, Wo, Wc);
}

// round 6
// speedup vs baseline: 1.1890x; 1.1890x over previous
#include <cuda_runtime.h>
#include <cuda_bf16.h>
#include <cstdint>

#define B_   64
#define T_   512
#define I_   512
#define H_   512
#define G4   2048
#define NC   64
#define BG4  (B_ * G4)

// ------------------------- device scratch ----------------------------------
__device__ float    g_WxHi[I_ * G4];                  // [k][n] tf32 hi (K1)
__device__ float    g_WxLo[I_ * G4];                  // [k][n] tf32 lo (K1)
__device__ float    g_bias[G4];
__device__ float    g_xproj[(size_t)T_ * BG4];        // [t][b][n] fp32
__device__ uint32_t g_hHi[(size_t)(T_ + 1) * B_ * 256];  // [t][b][k2] bf16x2 hi
__device__ uint32_t g_hLo[(size_t)(T_ + 1) * B_ * 256];  // [t][b][k2] bf16x2 lo
__device__ int      g_count;                          // grid barrier (monotonic)

// ------------------------- helpers -----------------------------------------
__device__ __forceinline__ float to_tf32(float x) {
    uint32_t u;
    asm("cvt.rna.tf32.f32 %0, %1;" : "=r"(u) : "f"(x));
    return __uint_as_float(u);
}
__device__ __forceinline__ float2 split2(float v) {
    float hi = to_tf32(v);
    float lo = to_tf32(v - hi);
    return make_float2(hi, lo);
}
__device__ __forceinline__ uint32_t fu(float x) { return __float_as_uint(x); }

// bf16 split: v ~= hi + lo, each bf16
__device__ __forceinline__ void bsplit(float v, uint16_t& hi, uint16_t& lo) {
    __nv_bfloat16 h = __float2bfloat16_rn(v);
    float r = v - __bfloat162float(h);
    __nv_bfloat16 l = __float2bfloat16_rn(r);
    hi = __bfloat16_as_ushort(h);
    lo = __bfloat16_as_ushort(l);
}
__device__ __forceinline__ uint32_t bpack(uint16_t e0, uint16_t e1) {   // e0 = lower k
    return (uint32_t)e0 | ((uint32_t)e1 << 16);
}

__device__ __forceinline__ float sigm(float x) { return 1.0f / (1.0f + __expf(-x)); }
__device__ __forceinline__ float tanh_acc(float x) {
    return 1.0f - 2.0f / (__expf(2.0f * x) + 1.0f);
}

__device__ __forceinline__ int ld_cg_int(const int* p) {
    int v;
    asm volatile("ld.global.cg.b32 %0, [%1];" : "=r"(v) : "l"(p));
    return v;
}

__device__ __forceinline__ void mma_tf32(float (&d)[4], const uint32_t (&a)[4],
                                         uint32_t b0, uint32_t b1) {
    asm volatile(
        "mma.sync.aligned.m16n8k8.row.col.f32.tf32.tf32.f32 "
        "{%0,%1,%2,%3}, {%4,%5,%6,%7}, {%8,%9}, {%0,%1,%2,%3};"
        : "+f"(d[0]), "+f"(d[1]), "+f"(d[2]), "+f"(d[3])
        : "r"(a[0]), "r"(a[1]), "r"(a[2]), "r"(a[3]), "r"(b0), "r"(b1));
}
__device__ __forceinline__ void mma_bf16(float (&d)[4], const uint32_t (&a)[4],
                                         uint32_t b0, uint32_t b1) {
    asm volatile(
        "mma.sync.aligned.m16n8k16.row.col.f32.bf16.bf16.f32 "
        "{%0,%1,%2,%3}, {%4,%5,%6,%7}, {%8,%9}, {%0,%1,%2,%3};"
        : "+f"(d[0]), "+f"(d[1]), "+f"(d[2]), "+f"(d[3])
        : "r"(a[0]), "r"(a[1]), "r"(a[2]), "r"(a[3]), "r"(b0), "r"(b1));
}

__device__ __forceinline__ const float* wsel(int gate, const float* Wf, const float* Wi,
                                             const float* Wo, const float* Wc) {
    return gate == 0 ? Wf : gate == 1 ? Wi : gate == 2 ? Wo : Wc;
}

// ------------------------- K0: pack ----------------------------------------
__global__ void pack_kernel(const float* __restrict__ Wf, const float* __restrict__ Wi,
                            const float* __restrict__ Wo, const float* __restrict__ Wc,
                            const float* __restrict__ bf, const float* __restrict__ bi,
                            const float* __restrict__ bo, const float* __restrict__ bc) {
    int idx = blockIdx.x * blockDim.x + threadIdx.x;
    if (idx < I_ * G4) {
        int n = idx & (G4 - 1), k = idx >> 11;
        int gate = n >> 9, j = n & 511;
        const float* W = wsel(gate, Wf, Wi, Wo, Wc);
        float2 s = split2(W[(size_t)k * H_ + j]);
        g_WxHi[idx] = s.x;
        g_WxLo[idx] = s.y;
    }
    if (idx < G4) {
        int gate = idx >> 9, j = idx & 511;
        const float* b = gate == 0 ? bf : gate == 1 ? bi : gate == 2 ? bo : bc;
        g_bias[idx] = b[j];
    }
    if (idx < B_ * 256) { g_hHi[idx] = 0u; g_hLo[idx] = 0u; }   // h_0 = 0
    if (idx == 0) g_count = 0;
}

// ------------------------- K1: xproj = X @ Wx + bias (3xTF32) --------------
// (unchanged from passing round-5 kernel)
#define K1_SMEM ((4 * 2 * 2304) * 4)
__global__ void __launch_bounds__(128) xproj_kernel(const float* __restrict__ x) {
    extern __shared__ float sm1[];
    float* sAhi = sm1;             // [2][64*36]
    float* sAlo = sm1 + 4608;
    float* sBhi = sm1 + 9216;      // [2][32*72]
    float* sBlo = sm1 + 13824;

    const int tid = threadIdx.x;
    const int bx = blockIdx.x, by = blockIdx.y;
    const int lane = tid & 31, w = tid >> 5;
    const int g = lane >> 2, tg = lane & 3;
    const int mw = w & 1, nw = w >> 1;

    const int ar = tid >> 3, ac = (tid & 7) * 4;
    const int br = tid >> 4, bc = (tid & 15) * 4;
    const float* Abase = x + (size_t)ar * (T_ * I_) + (size_t)by * I_ + ac;
    const float* BHbase = g_WxHi + (size_t)br * G4 + bx * 64 + bc;
    const float* BLbase = g_WxLo + (size_t)br * G4 + bx * 64 + bc;

    float4 ra[4], rbh[4], rbl[4];
#pragma unroll
    for (int i = 0; i < 4; i++) {
        ra[i]  = __ldg((const float4*)(Abase + (size_t)(16 * i) * (T_ * I_)));
        rbh[i] = __ldg((const float4*)(BHbase + (size_t)(8 * i) * G4));
        rbl[i] = __ldg((const float4*)(BLbase + (size_t)(8 * i) * G4));
    }
#pragma unroll
    for (int i = 0; i < 4; i++) {
        float2 sx = split2(ra[i].x), sy = split2(ra[i].y);
        float2 sz = split2(ra[i].z), sw = split2(ra[i].w);
        *(float4*)&sAhi[(ar + 16 * i) * 36 + ac] = make_float4(sx.x, sy.x, sz.x, sw.x);
        *(float4*)&sAlo[(ar + 16 * i) * 36 + ac] = make_float4(sx.y, sy.y, sz.y, sw.y);
        *(float4*)&sBhi[(br + 8 * i) * 72 + bc] = rbh[i];
        *(float4*)&sBlo[(br + 8 * i) * 72 + bc] = rbl[i];
    }
    __syncthreads();

    float acc[2][4][4] = {};

    for (int kc = 0; kc < 16; kc++) {
        const int cb = kc & 1;
        const int abuf = cb * 2304, bbuf = cb * 2304;
        if (kc < 15) {
#pragma unroll
            for (int i = 0; i < 4; i++) {
                ra[i]  = __ldg((const float4*)(Abase + (size_t)(16 * i) * (T_ * I_) + (kc + 1) * 32));
                rbh[i] = __ldg((const float4*)(BHbase + (size_t)((kc + 1) * 32 + 8 * i) * G4));
                rbl[i] = __ldg((const float4*)(BLbase + (size_t)((kc + 1) * 32 + 8 * i) * G4));
            }
        }
#pragma unroll
        for (int kk = 0; kk < 32; kk += 8) {
            uint32_t ahi[2][4], alo[2][4];
#pragma unroll
            for (int mf = 0; mf < 2; mf++) {
                int r0 = mw * 32 + mf * 16 + g;
                ahi[mf][0] = fu(sAhi[abuf + r0 * 36 + kk + tg]);
                ahi[mf][1] = fu(sAhi[abuf + (r0 + 8) * 36 + kk + tg]);
                ahi[mf][2] = fu(sAhi[abuf + r0 * 36 + kk + tg + 4]);
                ahi[mf][3] = fu(sAhi[abuf + (r0 + 8) * 36 + kk + tg + 4]);
                alo[mf][0] = fu(sAlo[abuf + r0 * 36 + kk + tg]);
                alo[mf][1] = fu(sAlo[abuf + (r0 + 8) * 36 + kk + tg]);
                alo[mf][2] = fu(sAlo[abuf + r0 * 36 + kk + tg + 4]);
                alo[mf][3] = fu(sAlo[abuf + (r0 + 8) * 36 + kk + tg + 4]);
            }
#pragma unroll
            for (int nf = 0; nf < 4; nf++) {
                int col = nw * 32 + nf * 8 + g;
                uint32_t bh0 = fu(sBhi[bbuf + (kk + tg) * 72 + col]);
                uint32_t bh1 = fu(sBhi[bbuf + (kk + tg + 4) * 72 + col]);
                uint32_t bl0 = fu(sBlo[bbuf + (kk + tg) * 72 + col]);
                uint32_t bl1 = fu(sBlo[bbuf + (kk + tg + 4) * 72 + col]);
#pragma unroll
                for (int mf = 0; mf < 2; mf++) {
                    mma_tf32(acc[mf][nf], ahi[mf], bh0, bh1);
                    mma_tf32(acc[mf][nf], ahi[mf], bl0, bl1);
                    mma_tf32(acc[mf][nf], alo[mf], bh0, bh1);
                }
            }
        }
        if (kc < 15) {
            const int nb = (cb ^ 1) * 2304;
#pragma unroll
            for (int i = 0; i < 4; i++) {
                float2 sx = split2(ra[i].x), sy = split2(ra[i].y);
                float2 sz = split2(ra[i].z), sw = split2(ra[i].w);
                *(float4*)&sAhi[nb + (ar + 16 * i) * 36 + ac] = make_float4(sx.x, sy.x, sz.x, sw.x);
                *(float4*)&sAlo[nb + (ar + 16 * i) * 36 + ac] = make_float4(sx.y, sy.y, sz.y, sw.y);
                *(float4*)&sBhi[nb + (br + 8 * i) * 72 + bc] = rbh[i];
                *(float4*)&sBlo[nb + (br + 8 * i) * 72 + bc] = rbl[i];
            }
            __syncthreads();
        }
    }

    const size_t outbase = (size_t)by * BG4;
#pragma unroll
    for (int mf = 0; mf < 2; mf++)
#pragma unroll
        for (int nf = 0; nf < 4; nf++) {
            int r = mw * 32 + mf * 16 + g;
            int cg = bx * 64 + nw * 32 + nf * 8 + tg * 2;
            float2 bb = *(const float2*)&g_bias[cg];
            float2 v0 = {acc[mf][nf][0] + bb.x, acc[mf][nf][1] + bb.y};
            float2 v1 = {acc[mf][nf][2] + bb.x, acc[mf][nf][3] + bb.y};
            *(float2*)&g_xproj[outbase + (size_t)r * G4 + cg] = v0;
            *(float2*)&g_xproj[outbase + (size_t)(r + 8) * G4 + cg] = v1;
        }
}

// ------------------------- K2: persistent recurrence (3xBF16) ---------------
// 64 CTAs x 128 thr. CTA nc owns hidden units [8nc,8nc+8) x 4 gates.
// mma.m16n8k16 bf16, 3-product scheme (hi*hi + hi*lo + lo*hi).
// Whole h (hi/lo bf16x2-packed) resident in smem per step; no chunk pipeline.
// Grid barrier per step (validated in round 5).
#define SH_STR 260                       // uint32 stride, 260 % 32 == 4 (conflict-free)
#define SMEM2  (65536 + 2 * 64 * SH_STR * 4)

__global__ void __launch_bounds__(128, 1) lstm_kernel(
    float* __restrict__ out,
    const float* __restrict__ Wf, const float* __restrict__ Wi,
    const float* __restrict__ Wo, const float* __restrict__ Wc) {
    extern __shared__ char smemraw[];
    uint4*    sWf  = (uint4*)smemraw;                  // [32 kb][4 nf][32 lane]
    uint32_t* sHhi = (uint32_t*)(smemraw + 65536);     // [64][SH_STR]
    uint32_t* sHlo = sHhi + 64 * SH_STR;

    const int tid = threadIdx.x;
    const int nc = blockIdx.x;
    const int lane = tid & 31, w = tid >> 5;
    const int g = lane >> 2, tg = lane & 3;
    const int w16 = w * 16;
    const int j0 = nc * 8 + tg * 2;

    // ---- build Wh bf16 fragments in smem (encoder == decoder) ----
    // m16n8k16 B frag: b0={B[K0+2tg][g],B[K0+2tg+1][g]}, b1=same at k+8,
    // B[k][n] = W_gate[(I_+k)][nc*8+n]. Stored {b0hi,b1hi,b0lo,b1lo}.
#pragma unroll
    for (int kbi = 0; kbi < 8; kbi++) {
        const int kb = w * 8 + kbi;
        const int k0 = kb * 16 + 2 * tg;
#pragma unroll
        for (int nf = 0; nf < 4; nf++) {
            const float* W = wsel(nf, Wf, Wi, Wo, Wc);
            const size_t base = (size_t)(I_ + k0) * H_ + nc * 8 + g;
            float v00 = __ldg(&W[base]);
            float v01 = __ldg(&W[base + H_]);
            float v10 = __ldg(&W[base + 8 * H_]);
            float v11 = __ldg(&W[base + 9 * H_]);
            uint16_t h00, l00, h01, l01, h10, l10, h11, l11;
            bsplit(v00, h00, l00); bsplit(v01, h01, l01);
            bsplit(v10, h10, l10); bsplit(v11, h11, l11);
            uint4 frag;
            frag.x = bpack(h00, h01);   // b0 hi
            frag.y = bpack(h10, h11);   // b1 hi
            frag.z = bpack(l00, l01);   // b0 lo
            frag.w = bpack(l10, l11);   // b1 lo
            sWf[(kb * 4 + nf) * 32 + lane] = frag;
        }
    }
    __syncthreads();

    float cs[4] = {0.0f, 0.0f, 0.0f, 0.0f};

    // xproj prefetch for t = 0
    float2 xp[8];
#pragma unroll
    for (int gate = 0; gate < 4; gate++)
#pragma unroll
        for (int rr = 0; rr < 2; rr++) {
            int b = w16 + g + rr * 8;
            xp[gate * 2 + rr] =
                __ldg((const float2*)(g_xproj + (size_t)b * G4 + gate * 512 + j0));
        }

    for (int t = 0; t < T_; t++) {
        // ---- copy h_t (packed bf16x2 hi/lo) into smem ----
        const uint32_t* hsH = g_hHi + (size_t)t * (B_ * 256);
        const uint32_t* hsL = g_hLo + (size_t)t * (B_ * 256);
#pragma unroll 8
        for (int i = 0; i < 32; i++) {
            int idx = tid + i * 128;
            int b = idx >> 6, j4 = (idx & 63) * 4;
            uint4 vh = __ldcg((const uint4*)(hsH + b * 256 + j4));
            uint4 vl = __ldcg((const uint4*)(hsL + b * 256 + j4));
            *(uint4*)&sHhi[b * SH_STR + j4] = vh;
            *(uint4*)&sHlo[b * SH_STR + j4] = vl;
        }
        __syncthreads();

        // ---- GEMM: 32 k16-blocks x 4 gates x 3 passes ----
        float acc[4][4] = {};
        const int r0 = w16 + g;
#pragma unroll 8
        for (int kb = 0; kb < 32; kb++) {
            const int wa = kb * 8 + tg;
            uint32_t ahi[4], alo[4];
            ahi[0] = sHhi[r0 * SH_STR + wa];
            ahi[1] = sHhi[(r0 + 8) * SH_STR + wa];
            ahi[2] = sHhi[r0 * SH_STR + wa + 4];
            ahi[3] = sHhi[(r0 + 8) * SH_STR + wa + 4];
            alo[0] = sHlo[r0 * SH_STR + wa];
            alo[1] = sHlo[(r0 + 8) * SH_STR + wa];
            alo[2] = sHlo[r0 * SH_STR + wa + 4];
            alo[3] = sHlo[(r0 + 8) * SH_STR + wa + 4];
            const uint4* wfb = sWf + (kb * 4) * 32 + lane;
#pragma unroll
            for (int nf = 0; nf < 4; nf++) {
                uint4 wf = wfb[nf * 32];
                mma_bf16(acc[nf], ahi, wf.x, wf.y);
                mma_bf16(acc[nf], ahi, wf.z, wf.w);
                mma_bf16(acc[nf], alo, wf.x, wf.y);
            }
        }

        // ---- epilogue: gates + state update ----
        float hout[4];
#pragma unroll
        for (int rr = 0; rr < 2; rr++) {
#pragma unroll
            for (int p = 0; p < 2; p++) {
                int q = rr * 2 + p;
                float xf = p == 0 ? xp[0 + rr].x : xp[0 + rr].y;
                float xi = p == 0 ? xp[2 + rr].x : xp[2 + rr].y;
                float xo = p == 0 ? xp[4 + rr].x : xp[4 + rr].y;
                float xc = p == 0 ? xp[6 + rr].x : xp[6 + rr].y;
                float fg = sigm(acc[0][q] + xf);
                float ig = sigm(acc[1][q] + xi);
                float og = sigm(acc[2][q] + xo);
                float Cg = tanh_acc(acc[3][q] + xc);
                cs[q] = fg * cs[q] + ig * Cg;
                hout[q] = og * tanh_acc(cs[q]);
            }
        }

        if (t == T_ - 1) {
#pragma unroll
            for (int rr = 0; rr < 2; rr++) {
                int b = w16 + g + rr * 8;
                float2 v = {hout[rr * 2 + 0], hout[rr * 2 + 1]};
                *(float2*)&out[(size_t)b * H_ + j0] = v;
            }
            break;
        }

        // write h_{t+1} split into packed bf16x2 hi/lo (thread owns k-pair j0,j0+1)
        uint32_t* dH = g_hHi + (size_t)(t + 1) * (B_ * 256);
        uint32_t* dL = g_hLo + (size_t)(t + 1) * (B_ * 256);
#pragma unroll
        for (int rr = 0; rr < 2; rr++) {
            int b = w16 + g + rr * 8;
            uint16_t h0h, h0l, h1h, h1l;
            bsplit(hout[rr * 2 + 0], h0h, h0l);
            bsplit(hout[rr * 2 + 1], h1h, h1l);
            __stcg(&dH[b * 256 + nc * 4 + tg], bpack(h0h, h1h));
            __stcg(&dL[b * 256 + nc * 4 + tg], bpack(h0l, h1l));
        }

        // ---- grid barrier, xp prefetch in its shadow ----
        __threadfence();
        __syncthreads();
        if (tid == 0) atomicAdd(&g_count, 1);

        {
            const float* xsrc = g_xproj + (size_t)(t + 1) * BG4;
#pragma unroll
            for (int gate = 0; gate < 4; gate++)
#pragma unroll
                for (int rr = 0; rr < 2; rr++) {
                    int b = w16 + g + rr * 8;
                    xp[gate * 2 + rr] =
                        __ldg((const float2*)(xsrc + (size_t)b * G4 + gate * 512 + j0));
                }
        }

        if (tid == 0) {
            while (ld_cg_int(&g_count) < NC * (t + 1)) {}
            __threadfence();
        }
        __syncthreads();
    }
}

// ------------------------- launch ------------------------------------------
extern "C" void kernel_launch(void* const* d_in, const int* in_sizes, int n_in,
                              void* d_out, int out_size) {
    (void)in_sizes; (void)n_in; (void)out_size;
    const float* x  = (const float*)d_in[0];
    const float* Wf = (const float*)d_in[1];
    const float* bf = (const float*)d_in[2];
    const float* Wi = (const float*)d_in[3];
    const float* bi = (const float*)d_in[4];
    const float* Wo = (const float*)d_in[5];
    const float* bo = (const float*)d_in[6];
    const float* Wc = (const float*)d_in[7];
    const float* bc = (const float*)d_in[8];

    cudaFuncSetAttribute(xproj_kernel, cudaFuncAttributeMaxDynamicSharedMemorySize, K1_SMEM);
    cudaFuncSetAttribute(lstm_kernel, cudaFuncAttributeMaxDynamicSharedMemorySize, SMEM2);

    pack_kernel<<<4096, 256>>>(Wf, Wi, Wo, Wc, bf, bi, bo, bc);
    dim3 gx(32, 512);
    xproj_kernel<<<gx, 128, K1_SMEM>>>(x);
    lstm_kernel<<<NC, 128, SMEM2>>>((float*)d_out, Wf, Wi, Wo, Wc);
}

// round 7
// speedup vs baseline: 1.7834x; 1.5000x over previous
#include <cuda_runtime.h>
#include <cuda_bf16.h>
#include <cstdint>

#define B_   64
#define T_   512
#define I_   512
#define H_   512
#define G4   2048
#define NC2  128
#define BG4  (B_ * G4)

// ------------------------- device scratch ----------------------------------
__device__ uint4    g_WxFrag[32 * 256 * 32];            // [kb][ncf][lane] bf16 frags
__device__ float    g_bias[G4];
__device__ float    g_xproj[(size_t)T_ * BG4];          // [t][b][n] fp32
__device__ uint32_t g_hHi[2][B_ * 256];                 // [buf][b][k2] bf16x2 hi
__device__ uint32_t g_hLo[2][B_ * 256];                 // [buf][b][k2] bf16x2 lo
__device__ int      g_count;                            // grid barrier (monotonic)

// ------------------------- helpers -----------------------------------------
__device__ __forceinline__ void bsplit(float v, uint16_t& hi, uint16_t& lo) {
    __nv_bfloat16 h = __float2bfloat16_rn(v);
    float r = v - __bfloat162float(h);
    __nv_bfloat16 l = __float2bfloat16_rn(r);
    hi = __bfloat16_as_ushort(h);
    lo = __bfloat16_as_ushort(l);
}
__device__ __forceinline__ uint32_t bpack(uint16_t e0, uint16_t e1) {
    return (uint32_t)e0 | ((uint32_t)e1 << 16);
}

__device__ __forceinline__ float sigm(float x) { return 1.0f / (1.0f + __expf(-x)); }
__device__ __forceinline__ float tanh_acc(float x) {
    return 1.0f - 2.0f / (__expf(2.0f * x) + 1.0f);
}

__device__ __forceinline__ int ld_acq(const int* p) {
    int v;
    asm volatile("ld.acquire.gpu.global.b32 %0, [%1];" : "=r"(v) : "l"(p) : "memory");
    return v;
}
__device__ __forceinline__ void red_rel(int* p) {
    asm volatile("red.release.gpu.global.add.s32 [%0], %1;" :: "l"(p), "r"(1) : "memory");
}

__device__ __forceinline__ void mma_bf16(float (&d)[4], const uint32_t (&a)[4],
                                         uint32_t b0, uint32_t b1) {
    asm volatile(
        "mma.sync.aligned.m16n8k16.row.col.f32.bf16.bf16.f32 "
        "{%0,%1,%2,%3}, {%4,%5,%6,%7}, {%8,%9}, {%0,%1,%2,%3};"
        : "+f"(d[0]), "+f"(d[1]), "+f"(d[2]), "+f"(d[3])
        : "r"(a[0]), "r"(a[1]), "r"(a[2]), "r"(a[3]), "r"(b0), "r"(b1));
}

__device__ __forceinline__ const float* wsel(int gate, const float* Wf, const float* Wi,
                                             const float* Wo, const float* Wc) {
    return gate == 0 ? Wf : gate == 1 ? Wi : gate == 2 ? Wo : Wc;
}

// ------------------------- K0: pack ----------------------------------------
// Builds g_WxFrag with the SAME fragment contract verified in K2's builder:
// frag(kb, ncf, lane): k0 = kb*16 + 2tg, col = ncf*8 + g;
// {b0hi=pack(B[k0],B[k0+1]), b1hi=pack(B[k0+8],B[k0+9]), b0lo, b1lo}.
__global__ void pack_kernel(const float* __restrict__ Wf, const float* __restrict__ Wi,
                            const float* __restrict__ Wo, const float* __restrict__ Wc,
                            const float* __restrict__ bf, const float* __restrict__ bi,
                            const float* __restrict__ bo, const float* __restrict__ bc) {
    int idx = blockIdx.x * blockDim.x + threadIdx.x;
    if (idx < 32 * 256 * 32) {
        int lane = idx & 31, ncf = (idx >> 5) & 255, kb = idx >> 13;
        int g = lane >> 2, tg = lane & 3;
        int k0 = kb * 16 + 2 * tg;
        int col = ncf * 8 + g;
        int gate = col >> 9, j = col & 511;
        const float* W = wsel(gate, Wf, Wi, Wo, Wc);
        float v00 = W[(size_t)k0 * H_ + j];
        float v01 = W[(size_t)(k0 + 1) * H_ + j];
        float v10 = W[(size_t)(k0 + 8) * H_ + j];
        float v11 = W[(size_t)(k0 + 9) * H_ + j];
        uint16_t h00, l00, h01, l01, h10, l10, h11, l11;
        bsplit(v00, h00, l00); bsplit(v01, h01, l01);
        bsplit(v10, h10, l10); bsplit(v11, h11, l11);
        uint4 frag;
        frag.x = bpack(h00, h01);
        frag.y = bpack(h10, h11);
        frag.z = bpack(l00, l01);
        frag.w = bpack(l10, l11);
        g_WxFrag[idx] = frag;
    }
    if (idx < G4) {
        int gate = idx >> 9, j = idx & 511;
        const float* b = gate == 0 ? bf : gate == 1 ? bi : gate == 2 ? bo : bc;
        g_bias[idx] = b[j];
    }
    if (idx < B_ * 256) { g_hHi[0][idx] = 0u; g_hLo[0][idx] = 0u; }
    if (idx == 0) g_count = 0;
}

// ------------------------- K1: xproj = X @ Wx + bias (3xBF16) --------------
// C[32768, 2048]; BM=64 (batch), BN=64, BK=32. grid (32, 512). 4 warps.
// A: fp32 -> bf16 hi/lo packed pairs in smem (stride 20, conflict-free).
// B: fragment-major uint4 from g_WxFrag (verified contract).
#define K1_SMEM (4 * 4 * 1280 + 2 * 512 * 16)
__global__ void __launch_bounds__(128) xproj_kernel(const float* __restrict__ x) {
    extern __shared__ char sm1raw[];
    uint32_t* sAhi = (uint32_t*)sm1raw;                 // [2][64*20]
    uint32_t* sAlo = sAhi + 2 * 1280;
    uint4*    sBf  = (uint4*)(sm1raw + 4 * 4 * 1280);   // [2][512]

    const int tid = threadIdx.x;
    const int bx = blockIdx.x, by = blockIdx.y;
    const int lane = tid & 31, w = tid >> 5;
    const int g = lane >> 2, tg = lane & 3;
    const int mw = w & 1, nw = w >> 1;

    const int ar = tid >> 3, ac = (tid & 7) * 4;        // A loader
    const float* Abase = x + (size_t)ar * (T_ * I_) + (size_t)by * I_ + ac;

    float4 ra[4];
    uint4  rbf[4];
#pragma unroll
    for (int i = 0; i < 4; i++)
        ra[i] = __ldg((const float4*)(Abase + (size_t)(16 * i) * (T_ * I_)));
#pragma unroll
    for (int i = 0; i < 4; i++) {
        int idx = tid + i * 128;                        // 0..511
        int ln = idx & 31, nf = (idx >> 5) & 7, kbi = idx >> 8;
        rbf[i] = __ldg(&g_WxFrag[((size_t)(0 + kbi) * 256 + bx * 8 + nf) * 32 + ln]);
    }
#pragma unroll
    for (int i = 0; i < 4; i++) {
        uint16_t hx, lx, hy, ly, hz, lz, hw, lw;
        bsplit(ra[i].x, hx, lx); bsplit(ra[i].y, hy, ly);
        bsplit(ra[i].z, hz, lz); bsplit(ra[i].w, hw, lw);
        uint2 vh = {bpack(hx, hy), bpack(hz, hw)};
        uint2 vl = {bpack(lx, ly), bpack(lz, lw)};
        *(uint2*)&sAhi[(ar + 16 * i) * 20 + (ac >> 1)] = vh;
        *(uint2*)&sAlo[(ar + 16 * i) * 20 + (ac >> 1)] = vl;
        sBf[tid + i * 128] = rbf[i];
    }
    __syncthreads();

    float acc[2][4][4] = {};

    for (int kc = 0; kc < 16; kc++) {
        const int cb = kc & 1;
        const int abuf = cb * 1280;
        const int bbuf = cb * 512;
        if (kc < 15) {
#pragma unroll
            for (int i = 0; i < 4; i++)
                ra[i] = __ldg((const float4*)(Abase + (size_t)(16 * i) * (T_ * I_) + (kc + 1) * 32));
#pragma unroll
            for (int i = 0; i < 4; i++) {
                int idx = tid + i * 128;
                int ln = idx & 31, nf = (idx >> 5) & 7, kbi = idx >> 8;
                rbf[i] = __ldg(&g_WxFrag[((size_t)((kc + 1) * 2 + kbi) * 256 + bx * 8 + nf) * 32 + ln]);
            }
        }
#pragma unroll
        for (int kbi = 0; kbi < 2; kbi++) {
            uint32_t ahi[2][4], alo[2][4];
#pragma unroll
            for (int mf = 0; mf < 2; mf++) {
                int r0 = mw * 32 + mf * 16 + g;
                int wa = kbi * 8 + tg;
                ahi[mf][0] = sAhi[abuf + r0 * 20 + wa];
                ahi[mf][1] = sAhi[abuf + (r0 + 8) * 20 + wa];
                ahi[mf][2] = sAhi[abuf + r0 * 20 + wa + 4];
                ahi[mf][3] = sAhi[abuf + (r0 + 8) * 20 + wa + 4];
                alo[mf][0] = sAlo[abuf + r0 * 20 + wa];
                alo[mf][1] = sAlo[abuf + (r0 + 8) * 20 + wa];
                alo[mf][2] = sAlo[abuf + r0 * 20 + wa + 4];
                alo[mf][3] = sAlo[abuf + (r0 + 8) * 20 + wa + 4];
            }
#pragma unroll
            for (int nf = 0; nf < 4; nf++) {
                uint4 wf = sBf[bbuf + (kbi * 8 + nw * 4 + nf) * 32 + lane];
#pragma unroll
                for (int mf = 0; mf < 2; mf++) {
                    mma_bf16(acc[mf][nf], ahi[mf], wf.x, wf.y);
                    mma_bf16(acc[mf][nf], ahi[mf], wf.z, wf.w);
                    mma_bf16(acc[mf][nf], alo[mf], wf.x, wf.y);
                }
            }
        }
        if (kc < 15) {
            const int na = (cb ^ 1) * 1280;
            const int nb = (cb ^ 1) * 512;
            __syncthreads();
#pragma unroll
            for (int i = 0; i < 4; i++) {
                uint16_t hx, lx, hy, ly, hz, lz, hw, lw;
                bsplit(ra[i].x, hx, lx); bsplit(ra[i].y, hy, ly);
                bsplit(ra[i].z, hz, lz); bsplit(ra[i].w, hw, lw);
                uint2 vh = {bpack(hx, hy), bpack(hz, hw)};
                uint2 vl = {bpack(lx, ly), bpack(lz, lw)};
                *(uint2*)&sAhi[na + (ar + 16 * i) * 20 + (ac >> 1)] = vh;
                *(uint2*)&sAlo[na + (ar + 16 * i) * 20 + (ac >> 1)] = vl;
                sBf[nb + tid + i * 128] = rbf[i];
            }
            __syncthreads();
        }
    }

    const size_t outbase = (size_t)by * BG4;
#pragma unroll
    for (int mf = 0; mf < 2; mf++)
#pragma unroll
        for (int nf = 0; nf < 4; nf++) {
            int r = mw * 32 + mf * 16 + g;
            int cg = bx * 64 + nw * 32 + nf * 8 + tg * 2;
            float2 bb = *(const float2*)&g_bias[cg];
            float2 v0 = {acc[mf][nf][0] + bb.x, acc[mf][nf][1] + bb.y};
            float2 v1 = {acc[mf][nf][2] + bb.x, acc[mf][nf][3] + bb.y};
            *(float2*)&g_xproj[outbase + (size_t)r * G4 + cg] = v0;
            *(float2*)&g_xproj[outbase + (size_t)(r + 8) * G4 + cg] = v1;
        }
}

// ------------------------- K2: persistent recurrence (3xBF16) ---------------
// 128 CTAs x 128 thr. CTA (mb, jc): batch rows [32mb,+32), hidden units
// [8jc,+8) x 4 gates (32x32 tile). 4 warps = 2 m-slices x 2 k-halves;
// k-partials combined via smem. Release/acquire grid barrier per step.
#define STRA  260
#define SMEM2 (65536 + 2 * 32 * STRA * 4 + 2 * 32 * 17 * 4)

__global__ void __launch_bounds__(128, 1) lstm_kernel(
    float* __restrict__ out,
    const float* __restrict__ Wf, const float* __restrict__ Wi,
    const float* __restrict__ Wo, const float* __restrict__ Wc) {
    extern __shared__ char smemraw[];
    uint4*    sWf  = (uint4*)smemraw;                        // [32 kb][4 nf][32 lane]
    uint32_t* sAh  = (uint32_t*)(smemraw + 65536);           // [32][STRA]
    uint32_t* sAl  = sAh + 32 * STRA;
    float*    sRed = (float*)(smemraw + 65536 + 2 * 32 * STRA * 4);  // [2*32][17]

    const int tid = threadIdx.x;
    const int bxid = blockIdx.x;
    const int mb = bxid >> 6, jc = bxid & 63;
    const int lane = tid & 31, w = tid >> 5;
    const int g = lane >> 2, tg = lane & 3;
    const int mslice = w & 1, khalf = w >> 1;
    const int j0 = jc * 8 + tg * 2;

    // ---- build Wh bf16 fragments in smem (verified round-6 builder) ----
#pragma unroll
    for (int kbi = 0; kbi < 8; kbi++) {
        const int kb = w * 8 + kbi;
        const int k0 = kb * 16 + 2 * tg;
#pragma unroll
        for (int nf = 0; nf < 4; nf++) {
            const float* W = wsel(nf, Wf, Wi, Wo, Wc);
            const size_t base = (size_t)(I_ + k0) * H_ + jc * 8 + g;
            float v00 = __ldg(&W[base]);
            float v01 = __ldg(&W[base + H_]);
            float v10 = __ldg(&W[base + 8 * H_]);
            float v11 = __ldg(&W[base + 9 * H_]);
            uint16_t h00, l00, h01, l01, h10, l10, h11, l11;
            bsplit(v00, h00, l00); bsplit(v01, h01, l01);
            bsplit(v10, h10, l10); bsplit(v11, h11, l11);
            uint4 frag;
            frag.x = bpack(h00, h01);
            frag.y = bpack(h10, h11);
            frag.z = bpack(l00, l01);
            frag.w = bpack(l10, l11);
            sWf[(kb * 4 + nf) * 32 + lane] = frag;
        }
    }
    __syncthreads();

    float cs[4] = {0.0f, 0.0f, 0.0f, 0.0f};

    // xproj prefetch for t = 0 (epilogue warps only: khalf == 0)
    float2 xp[8];
    if (khalf == 0) {
#pragma unroll
        for (int gate = 0; gate < 4; gate++)
#pragma unroll
            for (int rr = 0; rr < 2; rr++) {
                int b = mb * 32 + mslice * 16 + g + rr * 8;
                xp[gate * 2 + rr] =
                    __ldg((const float2*)(g_xproj + (size_t)b * G4 + gate * 512 + j0));
            }
    }

    for (int t = 0; t < T_; t++) {
        // ---- copy this CTA's 32 h rows (hi+lo) into smem ----
        const uint32_t* hsH = g_hHi[t & 1];
        const uint32_t* hsL = g_hLo[t & 1];
#pragma unroll
        for (int i = 0; i < 16; i++) {
            int idx = tid + i * 128;           // 0..2047
            int r = idx >> 6, c4 = (idx & 63) * 4;
            uint4 vh = __ldcg((const uint4*)(hsH + (mb * 32 + r) * 256 + c4));
            uint4 vl = __ldcg((const uint4*)(hsL + (mb * 32 + r) * 256 + c4));
            *(uint4*)&sAh[r * STRA + c4] = vh;
            *(uint4*)&sAl[r * STRA + c4] = vl;
        }
        __syncthreads();

        // ---- GEMM: 16 k16-blocks (this k-half) x 4 gates x 3 passes ----
        float acc[4][4] = {};
        const int rb = mslice * 16 + g;
#pragma unroll 8
        for (int kbi = 0; kbi < 16; kbi++) {
            const int kb = khalf * 16 + kbi;
            const int wa = kb * 8 + tg;
            uint32_t ahi[4], alo[4];
            ahi[0] = sAh[rb * STRA + wa];
            ahi[1] = sAh[(rb + 8) * STRA + wa];
            ahi[2] = sAh[rb * STRA + wa + 4];
            ahi[3] = sAh[(rb + 8) * STRA + wa + 4];
            alo[0] = sAl[rb * STRA + wa];
            alo[1] = sAl[(rb + 8) * STRA + wa];
            alo[2] = sAl[rb * STRA + wa + 4];
            alo[3] = sAl[(rb + 8) * STRA + wa + 4];
            const uint4* wfb = sWf + (kb * 4) * 32 + lane;
#pragma unroll
            for (int nf = 0; nf < 4; nf++) {
                uint4 wf = wfb[nf * 32];
                mma_bf16(acc[nf], ahi, wf.x, wf.y);
                mma_bf16(acc[nf], ahi, wf.z, wf.w);
                mma_bf16(acc[nf], alo, wf.x, wf.y);
            }
        }

        // ---- combine k-halves ----
        if (khalf == 1) {
            float* rd = sRed + (mslice * 32 + lane) * 17;
#pragma unroll
            for (int nf = 0; nf < 4; nf++)
#pragma unroll
                for (int q = 0; q < 4; q++) rd[nf * 4 + q] = acc[nf][q];
        }
        __syncthreads();

        float hout[4];
        if (khalf == 0) {
            const float* rd = sRed + (mslice * 32 + lane) * 17;
#pragma unroll
            for (int nf = 0; nf < 4; nf++)
#pragma unroll
                for (int q = 0; q < 4; q++) acc[nf][q] += rd[nf * 4 + q];

            // ---- epilogue: gates + state update ----
#pragma unroll
            for (int rr = 0; rr < 2; rr++) {
#pragma unroll
                for (int p = 0; p < 2; p++) {
                    int q = rr * 2 + p;
                    float xf = p == 0 ? xp[0 + rr].x : xp[0 + rr].y;
                    float xi = p == 0 ? xp[2 + rr].x : xp[2 + rr].y;
                    float xo = p == 0 ? xp[4 + rr].x : xp[4 + rr].y;
                    float xc = p == 0 ? xp[6 + rr].x : xp[6 + rr].y;
                    float fg = sigm(acc[0][q] + xf);
                    float ig = sigm(acc[1][q] + xi);
                    float og = sigm(acc[2][q] + xo);
                    float Cg = tanh_acc(acc[3][q] + xc);
                    cs[q] = fg * cs[q] + ig * Cg;
                    hout[q] = og * tanh_acc(cs[q]);
                }
            }

            if (t == T_ - 1) {
#pragma unroll
                for (int rr = 0; rr < 2; rr++) {
                    int b = mb * 32 + mslice * 16 + g + rr * 8;
                    float2 v = {hout[rr * 2 + 0], hout[rr * 2 + 1]};
                    *(float2*)&out[(size_t)b * H_ + j0] = v;
                }
            } else {
                uint32_t* dH = g_hHi[(t + 1) & 1];
                uint32_t* dL = g_hLo[(t + 1) & 1];
#pragma unroll
                for (int rr = 0; rr < 2; rr++) {
                    int b = mb * 32 + mslice * 16 + g + rr * 8;
                    uint16_t h0h, h0l, h1h, h1l;
                    bsplit(hout[rr * 2 + 0], h0h, h0l);
                    bsplit(hout[rr * 2 + 1], h1h, h1l);
                    __stcg(&dH[b * 256 + jc * 4 + tg], bpack(h0h, h1h));
                    __stcg(&dL[b * 256 + jc * 4 + tg], bpack(h0l, h1l));
                }
            }
        }
        if (t == T_ - 1) break;

        // ---- grid barrier (release/acquire), xp prefetch in its shadow ----
        __syncthreads();                      // all h stores program-ordered before arrive
        if (tid == 0) red_rel(&g_count);      // release: prior CTA stores visible

        if (khalf == 0) {                     // prefetch xproj for t+1 (h-independent)
            const float* xsrc = g_xproj + (size_t)(t + 1) * BG4;
#pragma unroll
            for (int gate = 0; gate < 4; gate++)
#pragma unroll
                for (int rr = 0; rr < 2; rr++) {
                    int b = mb * 32 + mslice * 16 + g + rr * 8;
                    xp[gate * 2 + rr] =
                        __ldg((const float2*)(xsrc + (size_t)b * G4 + gate * 512 + j0));
                }
        }

        if (tid == 0) {
            while (ld_acq(&g_count) < NC2 * (t + 1)) {}
        }
        __syncthreads();
    }
}

// ------------------------- launch ------------------------------------------
extern "C" void kernel_launch(void* const* d_in, const int* in_sizes, int n_in,
                              void* d_out, int out_size) {
    (void)in_sizes; (void)n_in; (void)out_size;
    const float* x  = (const float*)d_in[0];
    const float* Wf = (const float*)d_in[1];
    const float* bf = (const float*)d_in[2];
    const float* Wi = (const float*)d_in[3];
    const float* bi = (const float*)d_in[4];
    const float* Wo = (const float*)d_in[5];
    const float* bo = (const float*)d_in[6];
    const float* Wc = (const float*)d_in[7];
    const float* bc = (const float*)d_in[8];

    cudaFuncSetAttribute(xproj_kernel, cudaFuncAttributeMaxDynamicSharedMemorySize, K1_SMEM);
    cudaFuncSetAttribute(lstm_kernel, cudaFuncAttributeMaxDynamicSharedMemorySize, SMEM2);

    pack_kernel<<<4096, 256>>>(Wf, Wi, Wo, Wc, bf, bi, bo, bc);
    dim3 gx(32, 512);
    xproj_kernel<<<gx, 128, K1_SMEM>>>(x);
    lstm_kernel<<<NC2, 128, SMEM2>>>((float*)d_out, Wf, Wi, Wo, Wc);
}